// round 16
// baseline (speedup 1.0000x reference)
#include <cuda_runtime.h>
#include <cuda_fp16.h>
#include <math.h>
#include <stdint.h>

#define NN   8192
#define SQ   4
#define DIM  512
#define NH   4
#define DH   128
#define ET   73728
#define BOUT 128

#define M0MAX 32768          // max layer-0 active edges (expected ~11.5K)
#define M1MAX 4096           // max layer-1 active edges (expected ~1.15K)
#define C0MAX 8192
#define C0GRID 132           // ceil(4*(128+M1MAX)/128)
#define NBLK  1184

// ---------------- scratch (device globals; no runtime alloc allowed) -------
__device__ float  g_node_raw[NN * 8];
__device__ float  g_node_pos[(NN + 128) * DIM];            // +pad for scatter dummy
__device__ __half g_Xth[(NN + 128) * DIM];                 // compact node mlp hidden
__device__ __half g_Xh [((size_t)SQ * NN + 128) * DIM];
__device__ __half g_QKVh[((size_t)SQ * NN + 128) * 3 * DIM];
__device__ __half g_ehc [(size_t)M0MAX * DIM];
__device__ __half g_e0c [(size_t)M0MAX * DIM];
__device__ __half g_Ew1c[(size_t)M0MAX * 2 * DIM];
__device__ __half g_e1c [((size_t)4 * M1MAX + 128) * DIM];
__device__ __half g_Ew2c[((size_t)4 * M1MAX + 128) * 2 * DIM];
__device__ float  g_lg0[(size_t)M0MAX * SQ * NH];          // compact layer-0 logits
__device__ float  g_lg1[(size_t)4 * M1MAX * NH];           // compact layer-1 logits
__device__ __half g_Wpackth[2 * 3 * DIM * DIM];
__device__ __half g_wn2th[DIM * DIM];
__device__ __half g_wp2th[DIM * DIM];
__device__ __half g_WEth[2 * 2 * DIM * DIM];
// dst-CSR + frontier structures
__device__ int g_cnt[NN];
__device__ int g_cur[NN];
__device__ int g_off[NN + 1];
__device__ int g_eid[M0MAX];
__device__ int g_flag1[NN];
__device__ int g_flag0[NN];
__device__ int g_flag2[NN];
__device__ int g_pos1[ET];
__device__ int g_pos0[ET];         // e -> r in eL0 (only read for flag0 edges)
__device__ int g_eL1[M1MAX];
__device__ int g_eL0[M0MAX];
__device__ int g_nL0[C0MAX];
__device__ int g_nL2[NN + 128];
__device__ int g_rowIdxQ[4 * C0MAX + 128];
__device__ int g_rowIdx2[4 * NN + 128];
__device__ int g_m1, g_m0, g_c0, g_c2;

// ---------------- merged reset (one launch) ----------------------------------
__global__ void k_reset() {
    int i = blockIdx.x * blockDim.x + threadIdx.x;
    if (i == 0) { g_m1 = 0; g_m0 = 0; g_c0 = 0; g_c2 = 0; }
    if (i < NN) {
        g_cnt[i] = 0; g_cur[i] = 0;
        g_flag1[i] = 0; g_flag0[i] = 0; g_flag2[i] = 0;
    }
    if (i < NN * 8) g_node_raw[i] = 0.f;
    if (i < ET) g_pos1[i] = -1;
    if (i < 4 * C0MAX + 128) g_rowIdxQ[i] = SQ * NN;
    if (i < 4 * NN + 128) g_rowIdx2[i] = SQ * NN;
    if (i < NN + 128) g_nL2[i] = NN;              // dummy scatter row for node GEMM
}

// ---------------- merged weight pack (one launch) ----------------------------
#define SEG0 (512 * 512)
#define SEG1 (512 * 512)
#define SEG2 (2 * 1024 * 512)
#define SEG3 (2 * 1536 * 512)
__global__ void k_packall(const float* __restrict__ wn_w2, const float* __restrict__ wp_w2,
                          const float* __restrict__ WE,
                          const float* __restrict__ WQ, const float* __restrict__ WK,
                          const float* __restrict__ WV) {
    int idx = blockIdx.x * blockDim.x + threadIdx.x;
    if (idx < SEG0) {
        int k = idx & 511, n = idx >> 9;
        g_wn2th[idx] = __float2half_rn(wn_w2[(size_t)k * 512 + n]);
        return;
    }
    idx -= SEG0;
    if (idx < SEG1) {
        int k = idx & 511, n = idx >> 9;
        g_wp2th[idx] = __float2half_rn(wp_w2[(size_t)k * 512 + n]);
        return;
    }
    idx -= SEG1;
    if (idx < SEG2) {
        int l = idx / (1024 * 512);
        int r = idx % (1024 * 512);
        int k = r & 511, n = r >> 9;
        g_WEth[idx] = __float2half_rn(WE[(size_t)l * 512 * 1024 + (size_t)k * 1024 + n]);
        return;
    }
    idx -= SEG2;
    if (idx < SEG3) {
        int k = idx & 511;
        int n = (idx >> 9) % 1536;
        int l = idx / (1536 * 512);
        const float* W = (n < 512) ? WQ : ((n < 1024) ? WK : WV);
        int nn = n & 511;
        g_Wpackth[idx] = __float2half_rn(W[(size_t)l * 512 * 512 + (size_t)k * 512 + nn]);
    }
}

// ---------------- fused ET-range pass: build0 + CSR count + selfloop ---------
__global__ void k_fuse_et(const int* __restrict__ ei, const float* __restrict__ emb) {
    int e = blockIdx.x * blockDim.x + threadIdx.x;
    if (e >= ET) return;
    int s = ei[e], d = ei[ET + e];
    if (s == d) {
        #pragma unroll
        for (int r = 0; r < 8; r++)
            atomicAdd(&g_node_raw[s * 8 + r], emb[e * 8 + r]);
    }
    if (g_flag0[d]) {
        int r = atomicAdd(&g_m0, 1);
        g_eL0[r] = e;
        g_pos0[e] = r;
        atomicExch(&g_flag2[s], 1);
        atomicAdd(&g_cnt[d], 1);
    }
}

__global__ void k_flag1(const int* __restrict__ mapping) {
    int b = blockIdx.x * blockDim.x + threadIdx.x;
    if (b >= BOUT) return;
    int n = mapping[b];
    atomicExch(&g_flag1[n], 1);
    atomicExch(&g_flag0[n], 1);
    atomicExch(&g_flag2[n], 1);
}
__global__ void k_build1(const int* __restrict__ src, const int* __restrict__ dst) {
    int e = blockIdx.x * blockDim.x + threadIdx.x;
    if (e >= ET) return;
    if (g_flag1[dst[e]]) {
        int r = atomicAdd(&g_m1, 1);
        g_eL1[r] = e;
        g_pos1[e] = r;
        atomicExch(&g_flag0[src[e]], 1);
        atomicExch(&g_flag2[src[e]], 1);
    }
}

__global__ void k_scan() {
    __shared__ int part[1024];
    int tid = threadIdx.x;
    int base = tid * 8;
    int loc[8];
    int s = 0;
    #pragma unroll
    for (int i = 0; i < 8; i++) { loc[i] = s; s += g_cnt[base + i]; }
    part[tid] = s;
    __syncthreads();
    #pragma unroll
    for (int off = 1; off < 1024; off <<= 1) {
        int v = (tid >= off) ? part[tid - off] : 0;
        __syncthreads();
        part[tid] += v;
        __syncthreads();
    }
    int pre = (tid > 0) ? part[tid - 1] : 0;
    #pragma unroll
    for (int i = 0; i < 8; i++) g_off[base + i] = pre + loc[i];
    if (tid == 1023) g_off[NN] = part[1023];
}

// fill CSR from the compact eL0 list (grid-stride over m0)
__global__ void k_fill(const int* __restrict__ dst) {
    const int stride = gridDim.x * blockDim.x;
    for (int r = blockIdx.x * blockDim.x + threadIdx.x; r < g_m0; r += stride) {
        int e = g_eL0[r];
        int d = dst[e];
        int pos = atomicAdd(&g_cur[d], 1);
        g_eid[g_off[d] + pos] = e;
    }
}

// fused NN-range pass: per-node segment sort + frontier node lists
__global__ void k_sortbuild() {
    int n = blockIdx.x * blockDim.x + threadIdx.x;
    if (n >= NN) return;
    int st = g_off[n], en = g_off[n + 1];
    for (int i = st + 1; i < en; i++) {
        int v = g_eid[i];
        int j = i - 1;
        while (j >= st && g_eid[j] > v) { g_eid[j + 1] = g_eid[j]; j--; }
        g_eid[j + 1] = v;
    }
    if (g_flag0[n]) {
        int r = atomicAdd(&g_c0, 1);
        g_nL0[r] = n;
        #pragma unroll
        for (int s = 0; s < SQ; s++) g_rowIdxQ[4 * r + s] = s * NN + n;
    }
    if (g_flag2[n]) {
        int r = atomicAdd(&g_c2, 1);
        g_nL2[r] = n;
        #pragma unroll
        for (int s = 0; s < SQ; s++) g_rowIdx2[4 * r + s] = s * NN + n;
    }
}

// ---------------- small kernels -----------------------------------------------
// node MLP hidden, compact rows over nL2
__global__ void k_mlp1h_n(const float* __restrict__ in, const float* __restrict__ w1,
                          const float* __restrict__ b1, __half* __restrict__ out) {
    const long long total = (long long)g_c2 * DIM;
    const long long stride = (long long)gridDim.x * blockDim.x;
    for (long long idx = (long long)blockIdx.x * blockDim.x + threadIdx.x;
         idx < total; idx += stride) {
        int r = (int)(idx >> 9), j = (int)(idx & 511);
        int n = g_nL2[r];
        const float* ip = in + (long long)n * 8;
        float acc = b1[j];
        #pragma unroll
        for (int q = 0; q < 8; q++) acc = fmaf(ip[q], w1[q * DIM + j], acc);
        out[idx] = __float2half_rn(fmaxf(acc, 0.f));
    }
}

__global__ void k_mlp1h_g(const float* __restrict__ emb, const float* __restrict__ w1,
                          const float* __restrict__ b1, __half* __restrict__ out) {
    const long long total = (long long)g_m0 * DIM;
    const long long stride = (long long)gridDim.x * blockDim.x;
    for (long long idx = (long long)blockIdx.x * blockDim.x + threadIdx.x;
         idx < total; idx += stride) {
        int r = (int)(idx >> 9), j = (int)(idx & 511);
        int e = g_eL0[r];
        const float* ip = emb + (long long)e * 8;
        float acc = b1[j];
        #pragma unroll
        for (int q = 0; q < 8; q++) acc = fmaf(ip[q], w1[q * DIM + j], acc);
        out[idx] = __float2half_rn(fmaxf(acc, 0.f));
    }
}

__global__ void k_add_g(const float* __restrict__ query, const float* __restrict__ npos,
                        __half* __restrict__ X) {
    const long long total = (long long)g_c2 * SQ * DIM;
    const long long stride = (long long)gridDim.x * blockDim.x;
    for (long long idx = (long long)blockIdx.x * blockDim.x + threadIdx.x;
         idx < total; idx += stride) {
        int j = (int)(idx & 511);
        int s = (int)((idx >> 9) & 3);
        int r = (int)(idx >> 11);
        int n = g_nL2[r];
        X[((size_t)s * NN + n) * DIM + j] =
            __float2half_rn(query[(size_t)n * SQ * DIM + (size_t)s * DIM + j] +
                            npos[(size_t)n * DIM + j]);
    }
}

// ---------------- fp16 tensor-core GEMM core (ldmatrix fragments) -----------
#define BKH     32
#define KTOT    512
#define KSTEPS  (KTOT / BKH)
#define STG     3
#define STRH    40
#define OP_HALVES (128 * STRH)
#define GEMM_SMEM (STG * 2 * OP_HALVES * 2)

__device__ __forceinline__ void cp16(uint32_t dst, const void* src) {
    asm volatile("cp.async.cg.shared.global [%0], [%1], 16;\n" :: "r"(dst), "l"(src));
}
__device__ __forceinline__ void cp_commit() { asm volatile("cp.async.commit_group;\n"); }
__device__ __forceinline__ void cp_wait1()  { asm volatile("cp.async.wait_group 1;\n"); }

__device__ __forceinline__ void ldsm4(uint32_t& r0, uint32_t& r1, uint32_t& r2,
                                      uint32_t& r3, uint32_t addr) {
    asm volatile("ldmatrix.sync.aligned.m8n8.x4.shared.b16 {%0,%1,%2,%3}, [%4];"
                 : "=r"(r0), "=r"(r1), "=r"(r2), "=r"(r3) : "r"(addr));
}
__device__ __forceinline__ void mma_f16(float& c0, float& c1, float& c2, float& c3,
                                        uint32_t a0, uint32_t a1, uint32_t a2, uint32_t a3,
                                        uint32_t b0, uint32_t b1) {
    asm volatile("mma.sync.aligned.m16n8k16.row.col.f32.f16.f16.f32 "
                 "{%0,%1,%2,%3}, {%4,%5,%6,%7}, {%8,%9}, {%0,%1,%2,%3};\n"
                 : "+f"(c0), "+f"(c1), "+f"(c2), "+f"(c3)
                 : "r"(a0), "r"(a1), "r"(a2), "r"(a3), "r"(b0), "r"(b1));
}

__device__ __forceinline__ void gemm_core(const __half* const (&Ag)[2],
                                          const __half* const (&Bg)[2],
                                          __half* sh, float (&acc)[4][4][4]) {
    const int tid  = threadIdx.x;
    const int lane = tid & 31;
    const int warp = tid >> 5;
    const int wm = warp & 1;
    const int wn = warp >> 1;

    int rowL[2], cL[2];
    #pragma unroll
    for (int i = 0; i < 2; i++) {
        int ch = tid * 2 + i;
        rowL[i] = ch >> 2;
        cL[i]   = ch & 3;
    }
    const uint32_t suA = (uint32_t)__cvta_generic_to_shared(sh);
    const uint32_t suB = (uint32_t)__cvta_generic_to_shared(sh + STG * OP_HALVES);
    uint32_t aD[2], bD[2];
    #pragma unroll
    for (int i = 0; i < 2; i++) {
        aD[i] = suA + (uint32_t)(rowL[i] * STRH + cL[i] * 8) * 2u;
        bD[i] = suB + (uint32_t)(rowL[i] * STRH + cL[i] * 8) * 2u;
    }
    const uint32_t laneAoff = (uint32_t)(((lane & 7) + ((lane >> 3) & 1) * 8) * STRH
                                         + (lane >> 4) * 8);
    const uint32_t laneBoff = (uint32_t)(((lane & 7) + (lane >> 4) * 8) * STRH
                                         + ((lane >> 3) & 1) * 8);

    #pragma unroll
    for (int mt = 0; mt < 4; mt++)
        #pragma unroll
        for (int nt = 0; nt < 4; nt++)
            #pragma unroll
            for (int q = 0; q < 4; q++) acc[mt][nt][q] = 0.f;

    #pragma unroll
    for (int s = 0; s < 2; s++) {
        #pragma unroll
        for (int i = 0; i < 2; i++) {
            cp16(aD[i] + (uint32_t)(s * OP_HALVES * 2), Ag[i] + s * BKH);
            cp16(bD[i] + (uint32_t)(s * OP_HALVES * 2), Bg[i] + s * BKH);
        }
        cp_commit();
    }

    for (int kt = 0; kt < KSTEPS; kt++) {
        cp_wait1();
        __syncthreads();
        if (kt + 2 < KSTEPS) {
            const int st = (kt + 2) % STG;
            #pragma unroll
            for (int i = 0; i < 2; i++) {
                cp16(aD[i] + (uint32_t)(st * OP_HALVES * 2), Ag[i] + (kt + 2) * BKH);
                cp16(bD[i] + (uint32_t)(st * OP_HALVES * 2), Bg[i] + (kt + 2) * BKH);
            }
        }
        cp_commit();

        const uint32_t Ab = suA + (uint32_t)((kt % STG) * OP_HALVES) * 2u;
        const uint32_t Bb = suB + (uint32_t)((kt % STG) * OP_HALVES) * 2u;

        #pragma unroll
        for (int kk = 0; kk < BKH; kk += 16) {
            uint32_t af[4][4], bf[4][2];
            #pragma unroll
            for (int mt = 0; mt < 4; mt++) {
                uint32_t addr = Ab + 2u * (laneAoff + (uint32_t)((wm * 64 + mt * 16) * STRH + kk));
                ldsm4(af[mt][0], af[mt][1], af[mt][2], af[mt][3], addr);
            }
            #pragma unroll
            for (int p = 0; p < 2; p++) {
                uint32_t addr = Bb + 2u * (laneBoff + (uint32_t)((wn * 32 + p * 16) * STRH + kk));
                ldsm4(bf[2 * p][0], bf[2 * p][1], bf[2 * p + 1][0], bf[2 * p + 1][1], addr);
            }
            #pragma unroll
            for (int mt = 0; mt < 4; mt++)
                #pragma unroll
                for (int nt = 0; nt < 4; nt++)
                    mma_f16(acc[mt][nt][0], acc[mt][nt][1], acc[mt][nt][2], acc[mt][nt][3],
                            af[mt][0], af[mt][1], af[mt][2], af[mt][3],
                            bf[nt][0], bf[nt][1]);
        }
        __syncthreads();
    }
}

__global__ void __launch_bounds__(256, 2)
gemm_h(const __half* __restrict__ A, const __half* __restrict__ Bt,
       const float* __restrict__ bias, void* __restrict__ Cout,
       int N, int halfOut, const int* dynCnt, int dynMul) {
    extern __shared__ __half sh[];
    const long long bRow = (long long)blockIdx.y * 128;
    const long long bCol = (long long)blockIdx.x * 128;
    if (dynCnt) {
        int rows = dynMul * *dynCnt;
        if (bRow >= ((rows + 127) & ~127)) return;
    }
    const int tid  = threadIdx.x;
    const int lane = tid & 31;
    const int warp = tid >> 5;
    const int wm = warp & 1;
    const int wn = warp >> 1;
    const int g  = lane >> 2;
    const int t  = lane & 3;

    const __half* Ag[2];
    const __half* Bg[2];
    #pragma unroll
    for (int i = 0; i < 2; i++) {
        int ch = tid * 2 + i;
        int rowL = ch >> 2, cL = ch & 3;
        Ag[i] = A  + (bRow + rowL) * (long long)KTOT + cL * 8;
        Bg[i] = Bt + (bCol + rowL) * (long long)KTOT + cL * 8;
    }

    float acc[4][4][4];
    gemm_core(Ag, Bg, sh, acc);

    #pragma unroll
    for (int mt = 0; mt < 4; mt++) {
        #pragma unroll
        for (int nt = 0; nt < 4; nt++) {
            long long row0 = bRow + wm * 64 + mt * 16 + g;
            long long col  = bCol + wn * 32 + nt * 8 + t * 2;
            float b0 = 0.f, b1 = 0.f;
            if (bias) { b0 = bias[col]; b1 = bias[col + 1]; }
            float v00 = acc[mt][nt][0] + b0, v01 = acc[mt][nt][1] + b1;
            float v10 = acc[mt][nt][2] + b0, v11 = acc[mt][nt][3] + b1;
            if (halfOut) {
                __half2* C = (__half2*)Cout;
                C[(row0 * N + col) >> 1]       = __floats2half2_rn(v00, v01);
                C[((row0 + 8) * N + col) >> 1] = __floats2half2_rn(v10, v11);
            } else {
                float* C = (float*)Cout;
                *(float2*)(C + row0 * N + col)       = make_float2(v00, v01);
                *(float2*)(C + (row0 + 8) * N + col) = make_float2(v10, v11);
            }
        }
    }
}

// node GEMM: A compact rows, C scattered to node_pos[nL2[row]] (float, N=512)
__global__ void __launch_bounds__(256, 2)
gemm_nodeg(const __half* __restrict__ A, const __half* __restrict__ Bt,
           const float* __restrict__ bias, float* __restrict__ Cbase,
           const int* __restrict__ rowIdx, const int* dynCnt) {
    extern __shared__ __half sh[];
    const long long bRow = (long long)blockIdx.y * 128;
    const long long bCol = (long long)blockIdx.x * 128;
    {
        int rows = *dynCnt;
        if (bRow >= ((rows + 127) & ~127)) return;
    }
    const int tid  = threadIdx.x;
    const int lane = tid & 31;
    const int warp = tid >> 5;
    const int wm = warp & 1;
    const int wn = warp >> 1;
    const int g  = lane >> 2;
    const int t  = lane & 3;

    const __half* Ag[2];
    const __half* Bg[2];
    #pragma unroll
    for (int i = 0; i < 2; i++) {
        int ch = tid * 2 + i;
        int rowL = ch >> 2, cL = ch & 3;
        Ag[i] = A  + (bRow + rowL) * (long long)KTOT + cL * 8;
        Bg[i] = Bt + (bCol + rowL) * (long long)KTOT + cL * 8;
    }

    float acc[4][4][4];
    gemm_core(Ag, Bg, sh, acc);

    #pragma unroll
    for (int mt = 0; mt < 4; mt++) {
        int rl0 = wm * 64 + mt * 16 + g;
        size_t crow0 = (size_t)rowIdx[bRow + rl0] * DIM;
        size_t crow1 = (size_t)rowIdx[bRow + rl0 + 8] * DIM;
        #pragma unroll
        for (int nt = 0; nt < 4; nt++) {
            long long col = bCol + wn * 32 + nt * 8 + t * 2;
            float b0 = bias[col], b1 = bias[col + 1];
            *(float2*)(Cbase + crow0 + col) = make_float2(acc[mt][nt][0] + b0,
                                                          acc[mt][nt][1] + b1);
            *(float2*)(Cbase + crow1 + col) = make_float2(acc[mt][nt][2] + b0,
                                                          acc[mt][nt][3] + b1);
        }
    }
}

__global__ void __launch_bounds__(256, 2)
gemm_gather(const __half* __restrict__ Abase, const __half* __restrict__ Bt,
            __half* __restrict__ Cbase, const int* __restrict__ rowIdx,
            const int* dynCnt, int dynMul, int colOff) {
    extern __shared__ __half sh[];
    const long long bRow = (long long)blockIdx.y * 128;
    const long long bCol = (long long)blockIdx.x * 128;
    {
        int rows = dynMul * *dynCnt;
        if (bRow >= ((rows + 127) & ~127)) return;
    }
    const int tid  = threadIdx.x;
    const int lane = tid & 31;
    const int warp = tid >> 5;
    const int wm = warp & 1;
    const int wn = warp >> 1;
    const int g  = lane >> 2;
    const int t  = lane & 3;

    const __half* Ag[2];
    const __half* Bg[2];
    #pragma unroll
    for (int i = 0; i < 2; i++) {
        int ch = tid * 2 + i;
        int rowL = ch >> 2, cL = ch & 3;
        Ag[i] = Abase + (size_t)rowIdx[bRow + rowL] * KTOT + cL * 8;
        Bg[i] = Bt + (bCol + rowL) * (long long)KTOT + cL * 8;
    }

    float acc[4][4][4];
    gemm_core(Ag, Bg, sh, acc);

    #pragma unroll
    for (int mt = 0; mt < 4; mt++) {
        int rl0 = wm * 64 + mt * 16 + g;
        size_t crow0 = (size_t)rowIdx[bRow + rl0] * 1536 + colOff;
        size_t crow1 = (size_t)rowIdx[bRow + rl0 + 8] * 1536 + colOff;
        #pragma unroll
        for (int nt = 0; nt < 4; nt++) {
            long long col = bCol + wn * 32 + nt * 8 + t * 2;
            __half2* C = (__half2*)Cbase;
            C[(crow0 + col) >> 1] = __floats2half2_rn(acc[mt][nt][0], acc[mt][nt][1]);
            C[(crow1 + col) >> 1] = __floats2half2_rn(acc[mt][nt][2], acc[mt][nt][3]);
        }
    }
}

// ---------------- layer-0 compact edge kernel (loops s) ----------------------
__global__ void k_edge0c(const __half* __restrict__ QKV,
                         const int* __restrict__ src, const int* __restrict__ dst,
                         const float* __restrict__ aw) {
    const int lane = threadIdx.x & 31;
    const long long wtot = (long long)g_m0 * NH;
    const long long wstride = ((long long)gridDim.x * blockDim.x) >> 5;
    for (long long w = ((long long)blockIdx.x * blockDim.x + threadIdx.x) >> 5;
         w < wtot; w += wstride) {
        int r = (int)(w >> 2), h = (int)(w & 3);
        int e = g_eL0[r];
        int sn = src[e], dn = dst[e];
        int p1 = g_pos1[e];

        const __half2* ewp = (const __half2*)(g_Ew1c + (size_t)r * (2 * DIM) + h * 256);
        __half2 ew[2], eb[2];
        float a0[2], a1[2];
        #pragma unroll
        for (int i = 0; i < 2; i++) {
            int dd = lane + 32 * i;
            ew[i] = ewp[dd];
            eb[i] = ewp[dd + 64];
            a0[i] = aw[h * DH + 2 * dd];
            a1[i] = aw[h * DH + 2 * dd + 1];
        }
        #pragma unroll
        for (int s = 0; s < SQ; s++) {
            const __half2* qp = (const __half2*)(QKV + ((size_t)s * NN + dn) * (3 * DIM) + h * DH);
            const __half2* kp = (const __half2*)(QKV + ((size_t)s * NN + sn) * (3 * DIM) + DIM + h * DH);
            float lg = 0.f;
            float2 vals[2];
            #pragma unroll
            for (int i = 0; i < 2; i++) {
                int dd = lane + 32 * i;
                float2 kq = __half22float2(__hadd2(kp[dd], qp[dd]));
                float2 ewf = __half22float2(ew[i]);
                float2 ebf = __half22float2(eb[i]);
                float t0 = kq.x * ewf.x, t1 = kq.y * ewf.y;
                float s0 = (t0 >= 0.f) ? sqrtf(t0) : -sqrtf(-t0);
                float s1 = (t1 >= 0.f) ? sqrtf(t1) : -sqrtf(-t1);
                s0 = fmaxf(s0 + ebf.x, 0.f);
                s1 = fmaxf(s1 + ebf.y, 0.f);
                vals[i] = make_float2(s0, s1);
                lg = fmaf(s0, a0[i], lg);
                lg = fmaf(s1, a1[i], lg);
            }
            if (p1 >= 0) {
                __half2* op = (__half2*)(g_e1c + ((size_t)4 * p1 + s) * DIM + h * DH);
                #pragma unroll
                for (int i = 0; i < 2; i++)
                    op[lane + 32 * i] = __floats2half2_rn(vals[i].x, vals[i].y);
            }
            #pragma unroll
            for (int off = 16; off; off >>= 1) lg += __shfl_xor_sync(0xffffffffu, lg, off);
            if (lane == 0) g_lg0[((size_t)r * SQ + s) * NH + h] = lg;
        }
    }
}

// ---------------- layer-0 fused softmax+message over compact nodes -----------
__global__ void k_msg0(const __half* __restrict__ QKV, const int* __restrict__ src,
                       __half* __restrict__ Xh) {
    const int lane = threadIdx.x & 31;
    const long long wtot = (long long)g_c0 * SQ * NH;
    const long long wstride = ((long long)gridDim.x * blockDim.x) >> 5;
    for (long long w = ((long long)blockIdx.x * blockDim.x + threadIdx.x) >> 5;
         w < wtot; w += wstride) {
        int h = (int)(w & 3);
        int s = (int)((w >> 2) & 3);
        int r = (int)(w >> 4);
        int n = g_nL0[r];
        int st = g_off[n], en = g_off[n + 1];
        float m = -1e30f;
        for (int j = st; j < en; j++)
            m = fmaxf(m, g_lg0[((size_t)g_pos0[g_eid[j]] * SQ + s) * NH + h]);
        float z = 0.f;
        float a0x = 0.f, a0y = 0.f, a1x = 0.f, a1y = 0.f;
        for (int j = st; j < en; j++) {
            int e = g_eid[j];
            float wv = expf(g_lg0[((size_t)g_pos0[e] * SQ + s) * NH + h] - m);
            z += wv;
            const __half2* vp = (const __half2*)(QKV + ((size_t)s * NN + src[e]) * (3 * DIM)
                                                 + 2 * DIM + h * DH);
            float2 v0 = __half22float2(vp[lane]);
            float2 v1 = __half22float2(vp[lane + 32]);
            a0x = fmaf(v0.x, wv, a0x);
            a0y = fmaf(v0.y, wv, a0y);
            a1x = fmaf(v1.x, wv, a1x);
            a1y = fmaf(v1.y, wv, a1y);
        }
        float inv = 1.f / (z + 1e-16f);
        __half2* op = (__half2*)(Xh + ((size_t)s * NN + n) * DIM + h * DH);
        op[lane]      = __floats2half2_rn(a0x * inv, a0y * inv);
        op[lane + 32] = __floats2half2_rn(a1x * inv, a1y * inv);
    }
}

// ---------------- layer-1 compact edge kernel --------------------------------
__global__ void k_edge1c(const __half* __restrict__ QKV,
                         const int* __restrict__ src, const int* __restrict__ dst,
                         const float* __restrict__ aw) {
    const int lane = threadIdx.x & 31;
    const long long wtot = (long long)4 * g_m1 * NH;
    const long long wstride = ((long long)gridDim.x * blockDim.x) >> 5;
    for (long long w = ((long long)blockIdx.x * blockDim.x + threadIdx.x) >> 5;
         w < wtot; w += wstride) {
        int h = (int)(w & 3);
        int q = (int)(w >> 2);        // 4r+s
        int r = q >> 2, s = q & 3;
        int e = g_eL1[r];
        int sn = src[e], dn = dst[e];
        const __half2* qp  = (const __half2*)(QKV + ((size_t)s * NN + dn) * (3 * DIM) + h * DH);
        const __half2* kp  = (const __half2*)(QKV + ((size_t)s * NN + sn) * (3 * DIM) + DIM + h * DH);
        const __half2* ewp = (const __half2*)(g_Ew2c + (size_t)q * (2 * DIM) + h * 256);
        float lg = 0.f;
        #pragma unroll
        for (int i = 0; i < 2; i++) {
            int dd = lane + 32 * i;
            float2 kq = __half22float2(__hadd2(kp[dd], qp[dd]));
            float2 ewf = __half22float2(ewp[dd]);
            float2 ebf = __half22float2(ewp[dd + 64]);
            float t0 = kq.x * ewf.x, t1 = kq.y * ewf.y;
            float s0 = (t0 >= 0.f) ? sqrtf(t0) : -sqrtf(-t0);
            float s1 = (t1 >= 0.f) ? sqrtf(t1) : -sqrtf(-t1);
            s0 = fmaxf(s0 + ebf.x, 0.f);
            s1 = fmaxf(s1 + ebf.y, 0.f);
            lg = fmaf(s0, aw[h * DH + 2 * dd], lg);
            lg = fmaf(s1, aw[h * DH + 2 * dd + 1], lg);
        }
        #pragma unroll
        for (int off = 16; off; off >>= 1) lg += __shfl_xor_sync(0xffffffffu, lg, off);
        if (lane == 0) g_lg1[(size_t)q * NH + h] = lg;
    }
}

// ---------------- layer-1 fused softmax+message (mapped nodes) ---------------
__global__ void k_msg1(const __half* __restrict__ QKV, const int* __restrict__ src,
                       const int* __restrict__ mapping, float* __restrict__ out) {
    int w = (blockIdx.x * blockDim.x + threadIdx.x) >> 5;
    int lane = threadIdx.x & 31;
    if (w >= BOUT * SQ * NH) return;
    int h = w & 3;
    int s = (w >> 2) & 3;
    int b = w >> 4;
    int n = mapping[b];
    int st = g_off[n], en = g_off[n + 1];
    float m = -1e30f;
    for (int j = st; j < en; j++)
        m = fmaxf(m, g_lg1[(size_t)(4 * g_pos1[g_eid[j]] + s) * NH + h]);
    float z = 0.f;
    float a0x = 0.f, a0y = 0.f, a1x = 0.f, a1y = 0.f;
    for (int j = st; j < en; j++) {
        int e = g_eid[j];
        float wv = expf(g_lg1[(size_t)(4 * g_pos1[e] + s) * NH + h] - m);
        z += wv;
        const __half2* vp = (const __half2*)(QKV + ((size_t)s * NN + src[e]) * (3 * DIM)
                                             + 2 * DIM + h * DH);
        float2 v0 = __half22float2(vp[lane]);
        float2 v1 = __half22float2(vp[lane + 32]);
        a0x = fmaf(v0.x, wv, a0x);
        a0y = fmaf(v0.y, wv, a0y);
        a1x = fmaf(v1.x, wv, a1x);
        a1y = fmaf(v1.y, wv, a1y);
    }
    float inv = 1.f / (z + 1e-16f);
    float* op = out + ((size_t)b * SQ + s) * DIM + h * DH;
    op[2 * lane]            = a0x * inv;
    op[2 * lane + 1]        = a0y * inv;
    op[2 * (lane + 32)]     = a1x * inv;
    op[2 * (lane + 32) + 1] = a1y * inv;
}

// ---------------- host orchestration ---------------------------------------
extern "C" void kernel_launch(void* const* d_in, const int* in_sizes, int n_in,
                              void* d_out, int out_size) {
    const float* query   = (const float*)d_in[0];
    const int*   ei      = (const int*)  d_in[1];
    const int*   mapping = (const int*)  d_in[2];
    const float* emb     = (const float*)d_in[3];
    const float* wn_w1 = (const float*)d_in[5];
    const float* wn_b1 = (const float*)d_in[6];
    const float* wn_w2 = (const float*)d_in[7];
    const float* wn_b2 = (const float*)d_in[8];
    const float* wp_w1 = (const float*)d_in[9];
    const float* wp_b1 = (const float*)d_in[10];
    const float* wp_w2 = (const float*)d_in[11];
    const float* wp_b2 = (const float*)d_in[12];
    const float* WQ    = (const float*)d_in[13];
    const float* WK    = (const float*)d_in[14];
    const float* WV    = (const float*)d_in[15];
    const float* WE    = (const float*)d_in[16];
    const float* bE    = (const float*)d_in[17];
    const float* Aw    = (const float*)d_in[18];
    float* out = (float*)d_out;

    float  *node_raw, *node_pos;
    __half *Xth, *Xh, *QKVh, *ehc, *e0c, *Ew1c, *e1c, *Ew2c;
    __half *Wpackth, *wn2th, *wp2th, *WEth;
    int *rowIdxQ, *rowIdx2, *nL2, *pm1, *pm0, *pc0, *pc2;
    cudaGetSymbolAddress((void**)&node_raw, g_node_raw);
    cudaGetSymbolAddress((void**)&node_pos, g_node_pos);
    cudaGetSymbolAddress((void**)&Xth,  g_Xth);
    cudaGetSymbolAddress((void**)&Xh,   g_Xh);
    cudaGetSymbolAddress((void**)&QKVh, g_QKVh);
    cudaGetSymbolAddress((void**)&ehc,  g_ehc);
    cudaGetSymbolAddress((void**)&e0c,  g_e0c);
    cudaGetSymbolAddress((void**)&Ew1c, g_Ew1c);
    cudaGetSymbolAddress((void**)&e1c,  g_e1c);
    cudaGetSymbolAddress((void**)&Ew2c, g_Ew2c);
    cudaGetSymbolAddress((void**)&Wpackth, g_Wpackth);
    cudaGetSymbolAddress((void**)&wn2th, g_wn2th);
    cudaGetSymbolAddress((void**)&wp2th, g_wp2th);
    cudaGetSymbolAddress((void**)&WEth,  g_WEth);
    cudaGetSymbolAddress((void**)&rowIdxQ, g_rowIdxQ);
    cudaGetSymbolAddress((void**)&rowIdx2, g_rowIdx2);
    cudaGetSymbolAddress((void**)&nL2, g_nL2);
    cudaGetSymbolAddress((void**)&pm1, g_m1);
    cudaGetSymbolAddress((void**)&pm0, g_m0);
    cudaGetSymbolAddress((void**)&pc0, g_c0);
    cudaGetSymbolAddress((void**)&pc2, g_c2);

    cudaFuncSetAttribute(gemm_h, cudaFuncAttributeMaxDynamicSharedMemorySize, GEMM_SMEM);
    cudaFuncSetAttribute(gemm_gather, cudaFuncAttributeMaxDynamicSharedMemorySize, GEMM_SMEM);
    cudaFuncSetAttribute(gemm_nodeg, cudaFuncAttributeMaxDynamicSharedMemorySize, GEMM_SMEM);

    const int* srcp = ei;
    const int* dstp = ei + ET;
    const int T = 256;

    // ---- setup: reset, frontier, CSR (fused passes) ----
    k_reset<<<(ET + T - 1) / T, T>>>();
    k_flag1<<<1, BOUT>>>(mapping);
    k_build1<<<(ET + T - 1) / T, T>>>(srcp, dstp);
    k_fuse_et<<<(ET + T - 1) / T, T>>>(ei, emb);       // build0 + count + selfloop
    k_scan<<<1, 1024>>>();
    k_fill<<<(M0MAX + T - 1) / T, T>>>(dstp);          // compact-list fill
    k_sortbuild<<<(NN + T - 1) / T, T>>>();

    // ---- weight packs (1 launch) ----
    k_packall<<<(SEG0 + SEG1 + SEG2 + SEG3 + T - 1) / T, T>>>(wn_w2, wp_w2, WE, WQ, WK, WV);

    // ---- node path (restricted to frontier-2 nodes) ----
    k_mlp1h_n<<<NBLK, T>>>(node_raw, wn_w1, wn_b1, Xth);
    gemm_nodeg<<<dim3(DIM / 128, NN / 128), T, GEMM_SMEM>>>(Xth, wn2th, wn_b2,
                                                            node_pos, nL2, pc2);
    k_add_g<<<NBLK, T>>>(query, node_pos, Xh);

    // ---- compact edge feature chain ----
    k_mlp1h_g<<<NBLK, T>>>(emb, wp_w1, wp_b1, ehc);
    gemm_h<<<dim3(DIM / 128, M0MAX / 128), T, GEMM_SMEM>>>(ehc, wp2th, wp_b2, e0c,
                                                           DIM, 1, pm0, 1);
    gemm_h<<<dim3((2 * DIM) / 128, M0MAX / 128), T, GEMM_SMEM>>>(e0c, WEth, bE, Ew1c,
                                                                 2 * DIM, 1, pm0, 1);

    // ======== layer 0 ========
    gemm_gather<<<dim3(4, C0GRID), T, GEMM_SMEM>>>(
        Xh, Wpackth, QKVh, rowIdxQ, pc0, 4, 0);
    gemm_gather<<<dim3(8, (4 * NN) / 128), T, GEMM_SMEM>>>(
        Xh, Wpackth + (size_t)512 * 512, QKVh, rowIdx2, pc2, 4, 512);
    k_edge0c<<<NBLK, T>>>(QKVh, srcp, dstp, Aw);
    k_msg0<<<NBLK, T>>>(QKVh, srcp, Xh);

    // ======== layer 1 ========
    gemm_gather<<<dim3(12, C0GRID), T, GEMM_SMEM>>>(
        Xh, Wpackth + (size_t)1536 * 512, QKVh, rowIdxQ, pc0, 4, 0);
    gemm_h<<<dim3((2 * DIM) / 128, (4 * M1MAX) / 128), T, GEMM_SMEM>>>(
        e1c, WEth + 1024 * 512, bE + 2 * DIM, Ew2c, 2 * DIM, 1, pm1, 4);
    k_edge1c<<<NBLK, T>>>(QKVh, srcp, dstp, Aw + DIM);
    k_msg1<<<(BOUT * SQ * NH * 32) / T, T>>>(QKVh, srcp, mapping, out);
}

// round 17
// speedup vs baseline: 1.0475x; 1.0475x over previous
#include <cuda_runtime.h>
#include <cuda_fp16.h>
#include <math.h>
#include <stdint.h>

#define NN   8192
#define SQ   4
#define DIM  512
#define NH   4
#define DH   128
#define ET   73728
#define BOUT 128

#define M0MAX 32768
#define M1MAX 4096
#define C0MAX 8192
#define C0GRID 132           // ceil(4*(128+M1MAX)/128)
#define NBLK  1184

// ---------------- scratch (device globals; no runtime alloc allowed) -------
__device__ float  g_node_raw[NN * 8];
__device__ float  g_node_pos[(NN + 128) * DIM];
__device__ __half g_Xth[(NN + 128) * DIM];
__device__ __half g_Xh [((size_t)SQ * NN + 128) * DIM];
__device__ __half g_QKVh[((size_t)SQ * NN + 128) * 3 * DIM];
__device__ __half g_ehc [(size_t)M0MAX * DIM];
__device__ __half g_e0c [(size_t)M0MAX * DIM];
__device__ __half g_Ew1c[(size_t)M0MAX * 2 * DIM];
__device__ __half g_e1c [((size_t)4 * M1MAX + 128) * DIM];
__device__ __half g_Ew2c[((size_t)4 * M1MAX + 128) * 2 * DIM];
__device__ float  g_lg0[(size_t)M0MAX * SQ * NH];
__device__ float  g_lg1[(size_t)4 * M1MAX * NH];
__device__ __half g_Wpackth[2 * 3 * DIM * DIM];
__device__ __half g_wn2th[DIM * DIM];
__device__ __half g_wp2th[DIM * DIM];
__device__ __half g_WEth[2 * 2 * DIM * DIM];
// dst-CSR + frontier structures
__device__ int g_cnt[NN];
__device__ int g_cur[NN];
__device__ int g_off[NN + 1];
__device__ int g_eid[M0MAX];
__device__ int g_flag1[NN];
__device__ int g_flag0[NN];
__device__ int g_flag2[NN];
__device__ int g_pos1[ET];
__device__ int g_pos0[ET];
__device__ int g_eL1[M1MAX];
__device__ int g_eL0[M0MAX];
__device__ int g_nL0[C0MAX];
__device__ int g_nL2[NN + 128];
__device__ int g_rowIdxQ[4 * C0MAX + 128];
__device__ int g_rowIdx2[4 * NN + 128];
__device__ int g_m1, g_m0, g_c0, g_c2;

// ---------------- merged setup: reset + weight pack (one launch) -------------
#define SEG0 (512 * 512)
#define SEG1 (512 * 512)
#define SEG2 (2 * 1024 * 512)
#define SEG3 (2 * 1536 * 512)
#define PACKTOT (SEG0 + SEG1 + SEG2 + SEG3)
__global__ void k_setup(const float* __restrict__ wn_w2, const float* __restrict__ wp_w2,
                        const float* __restrict__ WE,
                        const float* __restrict__ WQ, const float* __restrict__ WK,
                        const float* __restrict__ WV) {
    const int i = blockIdx.x * blockDim.x + threadIdx.x;
    // ---- reset ----
    if (i == 0) { g_m1 = 0; g_m0 = 0; g_c0 = 0; g_c2 = 0; }
    if (i < NN) {
        g_cnt[i] = 0; g_cur[i] = 0;
        g_flag1[i] = 0; g_flag0[i] = 0; g_flag2[i] = 0;
    }
    if (i < NN * 8) g_node_raw[i] = 0.f;
    if (i < ET) g_pos1[i] = -1;
    if (i < 4 * C0MAX + 128) g_rowIdxQ[i] = SQ * NN;
    if (i < 4 * NN + 128) g_rowIdx2[i] = SQ * NN;
    if (i < NN + 128) g_nL2[i] = NN;
    // ---- pack ----
    int idx = i;
    if (idx < SEG0) {
        int k = idx & 511, n = idx >> 9;
        g_wn2th[idx] = __float2half_rn(wn_w2[(size_t)k * 512 + n]);
    } else if ((idx -= SEG0) < SEG1) {
        int k = idx & 511, n = idx >> 9;
        g_wp2th[idx] = __float2half_rn(wp_w2[(size_t)k * 512 + n]);
    } else if ((idx -= SEG1) < SEG2) {
        int l = idx / (1024 * 512);
        int r = idx % (1024 * 512);
        int k = r & 511, n = r >> 9;
        g_WEth[idx] = __float2half_rn(WE[(size_t)l * 512 * 1024 + (size_t)k * 1024 + n]);
    } else if ((idx -= SEG2) < SEG3) {
        int k = idx & 511;
        int n = (idx >> 9) % 1536;
        int l = idx / (1536 * 512);
        const float* W = (n < 512) ? WQ : ((n < 1024) ? WK : WV);
        int nn = n & 511;
        g_Wpackth[idx] = __float2half_rn(W[(size_t)l * 512 * 512 + (size_t)k * 512 + nn]);
    }
}

// ---------------- fused ET-range pass: build0 + CSR count + selfloop ---------
__global__ void k_fuse_et(const int* __restrict__ ei, const float* __restrict__ emb) {
    int e = blockIdx.x * blockDim.x + threadIdx.x;
    if (e >= ET) return;
    int s = ei[e], d = ei[ET + e];
    if (s == d) {
        #pragma unroll
        for (int r = 0; r < 8; r++)
            atomicAdd(&g_node_raw[s * 8 + r], emb[e * 8 + r]);
    }
    if (g_flag0[d]) {
        int r = atomicAdd(&g_m0, 1);
        g_eL0[r] = e;
        g_pos0[e] = r;
        atomicExch(&g_flag2[s], 1);
        atomicAdd(&g_cnt[d], 1);
    }
}

__global__ void k_flag1(const int* __restrict__ mapping) {
    int b = blockIdx.x * blockDim.x + threadIdx.x;
    if (b >= BOUT) return;
    int n = mapping[b];
    atomicExch(&g_flag1[n], 1);
    atomicExch(&g_flag0[n], 1);
    atomicExch(&g_flag2[n], 1);
}
__global__ void k_build1(const int* __restrict__ src, const int* __restrict__ dst) {
    int e = blockIdx.x * blockDim.x + threadIdx.x;
    if (e >= ET) return;
    if (g_flag1[dst[e]]) {
        int r = atomicAdd(&g_m1, 1);
        g_eL1[r] = e;
        g_pos1[e] = r;
        atomicExch(&g_flag0[src[e]], 1);
        atomicExch(&g_flag2[src[e]], 1);
    }
}

__global__ void k_scan() {
    __shared__ int part[1024];
    int tid = threadIdx.x;
    int base = tid * 8;
    int loc[8];
    int s = 0;
    #pragma unroll
    for (int i = 0; i < 8; i++) { loc[i] = s; s += g_cnt[base + i]; }
    part[tid] = s;
    __syncthreads();
    #pragma unroll
    for (int off = 1; off < 1024; off <<= 1) {
        int v = (tid >= off) ? part[tid - off] : 0;
        __syncthreads();
        part[tid] += v;
        __syncthreads();
    }
    int pre = (tid > 0) ? part[tid - 1] : 0;
    #pragma unroll
    for (int i = 0; i < 8; i++) g_off[base + i] = pre + loc[i];
    if (tid == 1023) g_off[NN] = part[1023];
}

__global__ void k_fill(const int* __restrict__ dst) {
    const int stride = gridDim.x * blockDim.x;
    for (int r = blockIdx.x * blockDim.x + threadIdx.x; r < g_m0; r += stride) {
        int e = g_eL0[r];
        int d = dst[e];
        int pos = atomicAdd(&g_cur[d], 1);
        g_eid[g_off[d] + pos] = e;
    }
}

__global__ void k_sortbuild() {
    int n = blockIdx.x * blockDim.x + threadIdx.x;
    if (n >= NN) return;
    int st = g_off[n], en = g_off[n + 1];
    for (int i = st + 1; i < en; i++) {
        int v = g_eid[i];
        int j = i - 1;
        while (j >= st && g_eid[j] > v) { g_eid[j + 1] = g_eid[j]; j--; }
        g_eid[j + 1] = v;
    }
    if (g_flag0[n]) {
        int r = atomicAdd(&g_c0, 1);
        g_nL0[r] = n;
        #pragma unroll
        for (int s = 0; s < SQ; s++) g_rowIdxQ[4 * r + s] = s * NN + n;
    }
    if (g_flag2[n]) {
        int r = atomicAdd(&g_c2, 1);
        g_nL2[r] = n;
        #pragma unroll
        for (int s = 0; s < SQ; s++) g_rowIdx2[4 * r + s] = s * NN + n;
    }
}

// ---------------- merged MLP pass: node hidden + edge hidden -----------------
__global__ void k_mlp_both(const float* __restrict__ node_raw, const float* __restrict__ wn1,
                           const float* __restrict__ bn1,
                           const float* __restrict__ emb, const float* __restrict__ wp1,
                           const float* __restrict__ bp1) {
    const long long nodeTot = (long long)g_c2 * DIM;
    const long long total = nodeTot + (long long)g_m0 * DIM;
    const long long stride = (long long)gridDim.x * blockDim.x;
    for (long long idx = (long long)blockIdx.x * blockDim.x + threadIdx.x;
         idx < total; idx += stride) {
        if (idx < nodeTot) {
            int r = (int)(idx >> 9), j = (int)(idx & 511);
            int n = g_nL2[r];
            const float* ip = node_raw + (long long)n * 8;
            float acc = bn1[j];
            #pragma unroll
            for (int q = 0; q < 8; q++) acc = fmaf(ip[q], wn1[q * DIM + j], acc);
            g_Xth[idx] = __float2half_rn(fmaxf(acc, 0.f));
        } else {
            long long idy = idx - nodeTot;
            int r = (int)(idy >> 9), j = (int)(idy & 511);
            int e = g_eL0[r];
            const float* ip = emb + (long long)e * 8;
            float acc = bp1[j];
            #pragma unroll
            for (int q = 0; q < 8; q++) acc = fmaf(ip[q], wp1[q * DIM + j], acc);
            g_ehc[idy] = __float2half_rn(fmaxf(acc, 0.f));
        }
    }
}

__global__ void k_add_g(const float* __restrict__ query, const float* __restrict__ npos,
                        __half* __restrict__ X) {
    const long long total = (long long)g_c2 * SQ * DIM;
    const long long stride = (long long)gridDim.x * blockDim.x;
    for (long long idx = (long long)blockIdx.x * blockDim.x + threadIdx.x;
         idx < total; idx += stride) {
        int j = (int)(idx & 511);
        int s = (int)((idx >> 9) & 3);
        int r = (int)(idx >> 11);
        int n = g_nL2[r];
        X[((size_t)s * NN + n) * DIM + j] =
            __float2half_rn(query[(size_t)n * SQ * DIM + (size_t)s * DIM + j] +
                            npos[(size_t)n * DIM + j]);
    }
}

// ---------------- fp16 tensor-core GEMM core (ldmatrix fragments) -----------
#define BKH     32
#define KTOT    512
#define KSTEPS  (KTOT / BKH)
#define STG     3
#define STRH    40
#define OP_HALVES (128 * STRH)
#define GEMM_SMEM (STG * 2 * OP_HALVES * 2)

__device__ __forceinline__ void cp16(uint32_t dst, const void* src) {
    asm volatile("cp.async.cg.shared.global [%0], [%1], 16;\n" :: "r"(dst), "l"(src));
}
__device__ __forceinline__ void cp_commit() { asm volatile("cp.async.commit_group;\n"); }
__device__ __forceinline__ void cp_wait1()  { asm volatile("cp.async.wait_group 1;\n"); }

__device__ __forceinline__ void ldsm4(uint32_t& r0, uint32_t& r1, uint32_t& r2,
                                      uint32_t& r3, uint32_t addr) {
    asm volatile("ldmatrix.sync.aligned.m8n8.x4.shared.b16 {%0,%1,%2,%3}, [%4];"
                 : "=r"(r0), "=r"(r1), "=r"(r2), "=r"(r3) : "r"(addr));
}
__device__ __forceinline__ void mma_f16(float& c0, float& c1, float& c2, float& c3,
                                        uint32_t a0, uint32_t a1, uint32_t a2, uint32_t a3,
                                        uint32_t b0, uint32_t b1) {
    asm volatile("mma.sync.aligned.m16n8k16.row.col.f32.f16.f16.f32 "
                 "{%0,%1,%2,%3}, {%4,%5,%6,%7}, {%8,%9}, {%0,%1,%2,%3};\n"
                 : "+f"(c0), "+f"(c1), "+f"(c2), "+f"(c3)
                 : "r"(a0), "r"(a1), "r"(a2), "r"(a3), "r"(b0), "r"(b1));
}

__device__ __forceinline__ void gemm_core(const __half* const (&Ag)[2],
                                          const __half* const (&Bg)[2],
                                          __half* sh, float (&acc)[4][4][4]) {
    const int tid  = threadIdx.x;
    const int lane = tid & 31;
    const int warp = tid >> 5;
    const int wm = warp & 1;
    const int wn = warp >> 1;

    int rowL[2], cL[2];
    #pragma unroll
    for (int i = 0; i < 2; i++) {
        int ch = tid * 2 + i;
        rowL[i] = ch >> 2;
        cL[i]   = ch & 3;
    }
    const uint32_t suA = (uint32_t)__cvta_generic_to_shared(sh);
    const uint32_t suB = (uint32_t)__cvta_generic_to_shared(sh + STG * OP_HALVES);
    uint32_t aD[2], bD[2];
    #pragma unroll
    for (int i = 0; i < 2; i++) {
        aD[i] = suA + (uint32_t)(rowL[i] * STRH + cL[i] * 8) * 2u;
        bD[i] = suB + (uint32_t)(rowL[i] * STRH + cL[i] * 8) * 2u;
    }
    const uint32_t laneAoff = (uint32_t)(((lane & 7) + ((lane >> 3) & 1) * 8) * STRH
                                         + (lane >> 4) * 8);
    const uint32_t laneBoff = (uint32_t)(((lane & 7) + (lane >> 4) * 8) * STRH
                                         + ((lane >> 3) & 1) * 8);

    #pragma unroll
    for (int mt = 0; mt < 4; mt++)
        #pragma unroll
        for (int nt = 0; nt < 4; nt++)
            #pragma unroll
            for (int q = 0; q < 4; q++) acc[mt][nt][q] = 0.f;

    #pragma unroll
    for (int s = 0; s < 2; s++) {
        #pragma unroll
        for (int i = 0; i < 2; i++) {
            cp16(aD[i] + (uint32_t)(s * OP_HALVES * 2), Ag[i] + s * BKH);
            cp16(bD[i] + (uint32_t)(s * OP_HALVES * 2), Bg[i] + s * BKH);
        }
        cp_commit();
    }

    for (int kt = 0; kt < KSTEPS; kt++) {
        cp_wait1();
        __syncthreads();
        if (kt + 2 < KSTEPS) {
            const int st = (kt + 2) % STG;
            #pragma unroll
            for (int i = 0; i < 2; i++) {
                cp16(aD[i] + (uint32_t)(st * OP_HALVES * 2), Ag[i] + (kt + 2) * BKH);
                cp16(bD[i] + (uint32_t)(st * OP_HALVES * 2), Bg[i] + (kt + 2) * BKH);
            }
        }
        cp_commit();

        const uint32_t Ab = suA + (uint32_t)((kt % STG) * OP_HALVES) * 2u;
        const uint32_t Bb = suB + (uint32_t)((kt % STG) * OP_HALVES) * 2u;

        #pragma unroll
        for (int kk = 0; kk < BKH; kk += 16) {
            uint32_t af[4][4], bf[4][2];
            #pragma unroll
            for (int mt = 0; mt < 4; mt++) {
                uint32_t addr = Ab + 2u * (laneAoff + (uint32_t)((wm * 64 + mt * 16) * STRH + kk));
                ldsm4(af[mt][0], af[mt][1], af[mt][2], af[mt][3], addr);
            }
            #pragma unroll
            for (int p = 0; p < 2; p++) {
                uint32_t addr = Bb + 2u * (laneBoff + (uint32_t)((wn * 32 + p * 16) * STRH + kk));
                ldsm4(bf[2 * p][0], bf[2 * p][1], bf[2 * p + 1][0], bf[2 * p + 1][1], addr);
            }
            #pragma unroll
            for (int mt = 0; mt < 4; mt++)
                #pragma unroll
                for (int nt = 0; nt < 4; nt++)
                    mma_f16(acc[mt][nt][0], acc[mt][nt][1], acc[mt][nt][2], acc[mt][nt][3],
                            af[mt][0], af[mt][1], af[mt][2], af[mt][3],
                            bf[nt][0], bf[nt][1]);
        }
        __syncthreads();
    }
}

__global__ void __launch_bounds__(256, 2)
gemm_h(const __half* __restrict__ A, const __half* __restrict__ Bt,
       const float* __restrict__ bias, void* __restrict__ Cout,
       int N, int halfOut, const int* dynCnt, int dynMul) {
    extern __shared__ __half sh[];
    const long long bRow = (long long)blockIdx.y * 128;
    const long long bCol = (long long)blockIdx.x * 128;
    if (dynCnt) {
        int rows = dynMul * *dynCnt;
        if (bRow >= ((rows + 127) & ~127)) return;
    }
    const int tid  = threadIdx.x;
    const int lane = tid & 31;
    const int warp = tid >> 5;
    const int wm = warp & 1;
    const int wn = warp >> 1;
    const int g  = lane >> 2;
    const int t  = lane & 3;

    const __half* Ag[2];
    const __half* Bg[2];
    #pragma unroll
    for (int i = 0; i < 2; i++) {
        int ch = tid * 2 + i;
        int rowL = ch >> 2, cL = ch & 3;
        Ag[i] = A  + (bRow + rowL) * (long long)KTOT + cL * 8;
        Bg[i] = Bt + (bCol + rowL) * (long long)KTOT + cL * 8;
    }

    float acc[4][4][4];
    gemm_core(Ag, Bg, sh, acc);

    #pragma unroll
    for (int mt = 0; mt < 4; mt++) {
        #pragma unroll
        for (int nt = 0; nt < 4; nt++) {
            long long row0 = bRow + wm * 64 + mt * 16 + g;
            long long col  = bCol + wn * 32 + nt * 8 + t * 2;
            float b0 = 0.f, b1 = 0.f;
            if (bias) { b0 = bias[col]; b1 = bias[col + 1]; }
            float v00 = acc[mt][nt][0] + b0, v01 = acc[mt][nt][1] + b1;
            float v10 = acc[mt][nt][2] + b0, v11 = acc[mt][nt][3] + b1;
            if (halfOut) {
                __half2* C = (__half2*)Cout;
                C[(row0 * N + col) >> 1]       = __floats2half2_rn(v00, v01);
                C[((row0 + 8) * N + col) >> 1] = __floats2half2_rn(v10, v11);
            } else {
                float* C = (float*)Cout;
                *(float2*)(C + row0 * N + col)       = make_float2(v00, v01);
                *(float2*)(C + (row0 + 8) * N + col) = make_float2(v10, v11);
            }
        }
    }
}

// node GEMM: A compact rows, C scattered to node_pos[nL2[row]] (float, N=512)
__global__ void __launch_bounds__(256, 2)
gemm_nodeg(const __half* __restrict__ A, const __half* __restrict__ Bt,
           const float* __restrict__ bias, float* __restrict__ Cbase,
           const int* __restrict__ rowIdx, const int* dynCnt) {
    extern __shared__ __half sh[];
    const long long bRow = (long long)blockIdx.y * 128;
    const long long bCol = (long long)blockIdx.x * 128;
    {
        int rows = *dynCnt;
        if (bRow >= ((rows + 127) & ~127)) return;
    }
    const int tid  = threadIdx.x;
    const int lane = tid & 31;
    const int warp = tid >> 5;
    const int wm = warp & 1;
    const int wn = warp >> 1;
    const int g  = lane >> 2;
    const int t  = lane & 3;

    const __half* Ag[2];
    const __half* Bg[2];
    #pragma unroll
    for (int i = 0; i < 2; i++) {
        int ch = tid * 2 + i;
        int rowL = ch >> 2, cL = ch & 3;
        Ag[i] = A  + (bRow + rowL) * (long long)KTOT + cL * 8;
        Bg[i] = Bt + (bCol + rowL) * (long long)KTOT + cL * 8;
    }

    float acc[4][4][4];
    gemm_core(Ag, Bg, sh, acc);

    #pragma unroll
    for (int mt = 0; mt < 4; mt++) {
        int rl0 = wm * 64 + mt * 16 + g;
        size_t crow0 = (size_t)rowIdx[bRow + rl0] * DIM;
        size_t crow1 = (size_t)rowIdx[bRow + rl0 + 8] * DIM;
        #pragma unroll
        for (int nt = 0; nt < 4; nt++) {
            long long col = bCol + wn * 32 + nt * 8 + t * 2;
            float b0 = bias[col], b1 = bias[col + 1];
            *(float2*)(Cbase + crow0 + col) = make_float2(acc[mt][nt][0] + b0,
                                                          acc[mt][nt][1] + b1);
            *(float2*)(Cbase + crow1 + col) = make_float2(acc[mt][nt][2] + b0,
                                                          acc[mt][nt][3] + b1);
        }
    }
}

// merged layer-0 gathers: blockIdx.x<4 -> Q (rowIdxQ, pc0), else KV (rowIdx2, pc2)
__global__ void __launch_bounds__(256, 2)
gemm_gather2(const __half* __restrict__ Abase,
             const __half* __restrict__ WQp, const __half* __restrict__ WKVp,
             __half* __restrict__ Cbase,
             const int* __restrict__ rowIdxQ, const int* __restrict__ rowIdx2,
             const int* pc0, const int* pc2) {
    extern __shared__ __half sh[];
    const int bx = blockIdx.x;
    const __half* Bt;
    const int* rowIdx;
    int colOff;
    long long bCol;
    int rows;
    if (bx < 4) { Bt = WQp;  rowIdx = rowIdxQ; colOff = 0;   bCol = (long long)bx * 128;       rows = 4 * *pc0; }
    else        { Bt = WKVp; rowIdx = rowIdx2; colOff = 512; bCol = (long long)(bx - 4) * 128; rows = 4 * *pc2; }
    const long long bRow = (long long)blockIdx.y * 128;
    if (bRow >= ((rows + 127) & ~127)) return;

    const int tid  = threadIdx.x;
    const int lane = tid & 31;
    const int warp = tid >> 5;
    const int wm = warp & 1;
    const int wn = warp >> 1;
    const int g  = lane >> 2;
    const int t  = lane & 3;

    const __half* Ag[2];
    const __half* Bg[2];
    #pragma unroll
    for (int i = 0; i < 2; i++) {
        int ch = tid * 2 + i;
        int rowL = ch >> 2, cL = ch & 3;
        Ag[i] = Abase + (size_t)rowIdx[bRow + rowL] * KTOT + cL * 8;
        Bg[i] = Bt + (bCol + rowL) * (long long)KTOT + cL * 8;
    }

    float acc[4][4][4];
    gemm_core(Ag, Bg, sh, acc);

    #pragma unroll
    for (int mt = 0; mt < 4; mt++) {
        int rl0 = wm * 64 + mt * 16 + g;
        size_t crow0 = (size_t)rowIdx[bRow + rl0] * 1536 + colOff;
        size_t crow1 = (size_t)rowIdx[bRow + rl0 + 8] * 1536 + colOff;
        #pragma unroll
        for (int nt = 0; nt < 4; nt++) {
            long long col = bCol + wn * 32 + nt * 8 + t * 2;
            __half2* C = (__half2*)Cbase;
            C[(crow0 + col) >> 1] = __floats2half2_rn(acc[mt][nt][0], acc[mt][nt][1]);
            C[(crow1 + col) >> 1] = __floats2half2_rn(acc[mt][nt][2], acc[mt][nt][3]);
        }
    }
}

// merged layer-1: blockIdx.x<12 -> QKV gather (rowIdxQ); else dense Ew2 GEMM
__global__ void __launch_bounds__(256, 2)
k_l1combo(const __half* __restrict__ Xh, const __half* __restrict__ Wqkv1,
          __half* __restrict__ QKV,
          const __half* __restrict__ e1c, const __half* __restrict__ WE1,
          const float* __restrict__ bE1, __half* __restrict__ Ew2c,
          const int* __restrict__ rowIdxQ, const int* pc0, const int* pm1) {
    extern __shared__ __half sh[];
    const int bx = blockIdx.x;
    const long long bRow = (long long)blockIdx.y * 128;
    const int tid  = threadIdx.x;
    const int lane = tid & 31;
    const int warp = tid >> 5;
    const int wm = warp & 1;
    const int wn = warp >> 1;
    const int g  = lane >> 2;
    const int t  = lane & 3;

    if (bx < 12) {
        int rows = 4 * *pc0;
        if (bRow >= ((rows + 127) & ~127)) return;
        const long long bCol = (long long)bx * 128;
        const __half* Ag[2];
        const __half* Bg[2];
        #pragma unroll
        for (int i = 0; i < 2; i++) {
            int ch = tid * 2 + i;
            int rowL = ch >> 2, cL = ch & 3;
            Ag[i] = Xh + (size_t)rowIdxQ[bRow + rowL] * KTOT + cL * 8;
            Bg[i] = Wqkv1 + (bCol + rowL) * (long long)KTOT + cL * 8;
        }
        float acc[4][4][4];
        gemm_core(Ag, Bg, sh, acc);
        #pragma unroll
        for (int mt = 0; mt < 4; mt++) {
            int rl0 = wm * 64 + mt * 16 + g;
            size_t crow0 = (size_t)rowIdxQ[bRow + rl0] * 1536;
            size_t crow1 = (size_t)rowIdxQ[bRow + rl0 + 8] * 1536;
            #pragma unroll
            for (int nt = 0; nt < 4; nt++) {
                long long col = bCol + wn * 32 + nt * 8 + t * 2;
                __half2* C = (__half2*)QKV;
                C[(crow0 + col) >> 1] = __floats2half2_rn(acc[mt][nt][0], acc[mt][nt][1]);
                C[(crow1 + col) >> 1] = __floats2half2_rn(acc[mt][nt][2], acc[mt][nt][3]);
            }
        }
    } else {
        int rows = 4 * *pm1;
        if (bRow >= ((rows + 127) & ~127)) return;
        const long long bCol = (long long)(bx - 12) * 128;
        const __half* Ag[2];
        const __half* Bg[2];
        #pragma unroll
        for (int i = 0; i < 2; i++) {
            int ch = tid * 2 + i;
            int rowL = ch >> 2, cL = ch & 3;
            Ag[i] = e1c + (bRow + rowL) * (long long)KTOT + cL * 8;
            Bg[i] = WE1 + (bCol + rowL) * (long long)KTOT + cL * 8;
        }
        float acc[4][4][4];
        gemm_core(Ag, Bg, sh, acc);
        #pragma unroll
        for (int mt = 0; mt < 4; mt++) {
            #pragma unroll
            for (int nt = 0; nt < 4; nt++) {
                long long row0 = bRow + wm * 64 + mt * 16 + g;
                long long col  = bCol + wn * 32 + nt * 8 + t * 2;
                float b0 = bE1[col], b1 = bE1[col + 1];
                __half2* C = (__half2*)Ew2c;
                C[(row0 * 1024 + col) >> 1] =
                    __floats2half2_rn(acc[mt][nt][0] + b0, acc[mt][nt][1] + b1);
                C[((row0 + 8) * 1024 + col) >> 1] =
                    __floats2half2_rn(acc[mt][nt][2] + b0, acc[mt][nt][3] + b1);
            }
        }
    }
}

// ---------------- layer-0 compact edge kernel (loops s) ----------------------
__global__ void k_edge0c(const __half* __restrict__ QKV,
                         const int* __restrict__ src, const int* __restrict__ dst,
                         const float* __restrict__ aw) {
    const int lane = threadIdx.x & 31;
    const long long wtot = (long long)g_m0 * NH;
    const long long wstride = ((long long)gridDim.x * blockDim.x) >> 5;
    for (long long w = ((long long)blockIdx.x * blockDim.x + threadIdx.x) >> 5;
         w < wtot; w += wstride) {
        int r = (int)(w >> 2), h = (int)(w & 3);
        int e = g_eL0[r];
        int sn = src[e], dn = dst[e];
        int p1 = g_pos1[e];

        const __half2* ewp = (const __half2*)(g_Ew1c + (size_t)r * (2 * DIM) + h * 256);
        __half2 ew[2], eb[2];
        float a0[2], a1[2];
        #pragma unroll
        for (int i = 0; i < 2; i++) {
            int dd = lane + 32 * i;
            ew[i] = ewp[dd];
            eb[i] = ewp[dd + 64];
            a0[i] = aw[h * DH + 2 * dd];
            a1[i] = aw[h * DH + 2 * dd + 1];
        }
        #pragma unroll
        for (int s = 0; s < SQ; s++) {
            const __half2* qp = (const __half2*)(QKV + ((size_t)s * NN + dn) * (3 * DIM) + h * DH);
            const __half2* kp = (const __half2*)(QKV + ((size_t)s * NN + sn) * (3 * DIM) + DIM + h * DH);
            float lg = 0.f;
            float2 vals[2];
            #pragma unroll
            for (int i = 0; i < 2; i++) {
                int dd = lane + 32 * i;
                float2 kq = __half22float2(__hadd2(kp[dd], qp[dd]));
                float2 ewf = __half22float2(ew[i]);
                float2 ebf = __half22float2(eb[i]);
                float t0 = kq.x * ewf.x, t1 = kq.y * ewf.y;
                float s0 = (t0 >= 0.f) ? sqrtf(t0) : -sqrtf(-t0);
                float s1 = (t1 >= 0.f) ? sqrtf(t1) : -sqrtf(-t1);
                s0 = fmaxf(s0 + ebf.x, 0.f);
                s1 = fmaxf(s1 + ebf.y, 0.f);
                vals[i] = make_float2(s0, s1);
                lg = fmaf(s0, a0[i], lg);
                lg = fmaf(s1, a1[i], lg);
            }
            if (p1 >= 0) {
                __half2* op = (__half2*)(g_e1c + ((size_t)4 * p1 + s) * DIM + h * DH);
                #pragma unroll
                for (int i = 0; i < 2; i++)
                    op[lane + 32 * i] = __floats2half2_rn(vals[i].x, vals[i].y);
            }
            #pragma unroll
            for (int off = 16; off; off >>= 1) lg += __shfl_xor_sync(0xffffffffu, lg, off);
            if (lane == 0) g_lg0[((size_t)r * SQ + s) * NH + h] = lg;
        }
    }
}

// ---------------- layer-0 fused softmax+message over compact nodes -----------
__global__ void k_msg0(const __half* __restrict__ QKV, const int* __restrict__ src,
                       __half* __restrict__ Xh) {
    const int lane = threadIdx.x & 31;
    const long long wtot = (long long)g_c0 * SQ * NH;
    const long long wstride = ((long long)gridDim.x * blockDim.x) >> 5;
    for (long long w = ((long long)blockIdx.x * blockDim.x + threadIdx.x) >> 5;
         w < wtot; w += wstride) {
        int h = (int)(w & 3);
        int s = (int)((w >> 2) & 3);
        int r = (int)(w >> 4);
        int n = g_nL0[r];
        int st = g_off[n], en = g_off[n + 1];
        float m = -1e30f;
        for (int j = st; j < en; j++)
            m = fmaxf(m, g_lg0[((size_t)g_pos0[g_eid[j]] * SQ + s) * NH + h]);
        float z = 0.f;
        float a0x = 0.f, a0y = 0.f, a1x = 0.f, a1y = 0.f;
        for (int j = st; j < en; j++) {
            int e = g_eid[j];
            float wv = expf(g_lg0[((size_t)g_pos0[e] * SQ + s) * NH + h] - m);
            z += wv;
            const __half2* vp = (const __half2*)(QKV + ((size_t)s * NN + src[e]) * (3 * DIM)
                                                 + 2 * DIM + h * DH);
            float2 v0 = __half22float2(vp[lane]);
            float2 v1 = __half22float2(vp[lane + 32]);
            a0x = fmaf(v0.x, wv, a0x);
            a0y = fmaf(v0.y, wv, a0y);
            a1x = fmaf(v1.x, wv, a1x);
            a1y = fmaf(v1.y, wv, a1y);
        }
        float inv = 1.f / (z + 1e-16f);
        __half2* op = (__half2*)(Xh + ((size_t)s * NN + n) * DIM + h * DH);
        op[lane]      = __floats2half2_rn(a0x * inv, a0y * inv);
        op[lane + 32] = __floats2half2_rn(a1x * inv, a1y * inv);
    }
}

// ---------------- layer-1 compact edge kernel --------------------------------
__global__ void k_edge1c(const __half* __restrict__ QKV,
                         const int* __restrict__ src, const int* __restrict__ dst,
                         const float* __restrict__ aw) {
    const int lane = threadIdx.x & 31;
    const long long wtot = (long long)4 * g_m1 * NH;
    const long long wstride = ((long long)gridDim.x * blockDim.x) >> 5;
    for (long long w = ((long long)blockIdx.x * blockDim.x + threadIdx.x) >> 5;
         w < wtot; w += wstride) {
        int h = (int)(w & 3);
        int q = (int)(w >> 2);        // 4r+s
        int r = q >> 2, s = q & 3;
        int e = g_eL1[r];
        int sn = src[e], dn = dst[e];
        const __half2* qp  = (const __half2*)(QKV + ((size_t)s * NN + dn) * (3 * DIM) + h * DH);
        const __half2* kp  = (const __half2*)(QKV + ((size_t)s * NN + sn) * (3 * DIM) + DIM + h * DH);
        const __half2* ewp = (const __half2*)(g_Ew2c + (size_t)q * (2 * DIM) + h * 256);
        float lg = 0.f;
        #pragma unroll
        for (int i = 0; i < 2; i++) {
            int dd = lane + 32 * i;
            float2 kq = __half22float2(__hadd2(kp[dd], qp[dd]));
            float2 ewf = __half22float2(ewp[dd]);
            float2 ebf = __half22float2(ewp[dd + 64]);
            float t0 = kq.x * ewf.x, t1 = kq.y * ewf.y;
            float s0 = (t0 >= 0.f) ? sqrtf(t0) : -sqrtf(-t0);
            float s1 = (t1 >= 0.f) ? sqrtf(t1) : -sqrtf(-t1);
            s0 = fmaxf(s0 + ebf.x, 0.f);
            s1 = fmaxf(s1 + ebf.y, 0.f);
            lg = fmaf(s0, aw[h * DH + 2 * dd], lg);
            lg = fmaf(s1, aw[h * DH + 2 * dd + 1], lg);
        }
        #pragma unroll
        for (int off = 16; off; off >>= 1) lg += __shfl_xor_sync(0xffffffffu, lg, off);
        if (lane == 0) g_lg1[(size_t)q * NH + h] = lg;
    }
}

// ---------------- layer-1 fused softmax+message (mapped nodes) ---------------
__global__ void k_msg1(const __half* __restrict__ QKV, const int* __restrict__ src,
                       const int* __restrict__ mapping, float* __restrict__ out) {
    int w = (blockIdx.x * blockDim.x + threadIdx.x) >> 5;
    int lane = threadIdx.x & 31;
    if (w >= BOUT * SQ * NH) return;
    int h = w & 3;
    int s = (w >> 2) & 3;
    int b = w >> 4;
    int n = mapping[b];
    int st = g_off[n], en = g_off[n + 1];
    float m = -1e30f;
    for (int j = st; j < en; j++)
        m = fmaxf(m, g_lg1[(size_t)(4 * g_pos1[g_eid[j]] + s) * NH + h]);
    float z = 0.f;
    float a0x = 0.f, a0y = 0.f, a1x = 0.f, a1y = 0.f;
    for (int j = st; j < en; j++) {
        int e = g_eid[j];
        float wv = expf(g_lg1[(size_t)(4 * g_pos1[e] + s) * NH + h] - m);
        z += wv;
        const __half2* vp = (const __half2*)(QKV + ((size_t)s * NN + src[e]) * (3 * DIM)
                                             + 2 * DIM + h * DH);
        float2 v0 = __half22float2(vp[lane]);
        float2 v1 = __half22float2(vp[lane + 32]);
        a0x = fmaf(v0.x, wv, a0x);
        a0y = fmaf(v0.y, wv, a0y);
        a1x = fmaf(v1.x, wv, a1x);
        a1y = fmaf(v1.y, wv, a1y);
    }
    float inv = 1.f / (z + 1e-16f);
    float* op = out + ((size_t)b * SQ + s) * DIM + h * DH;
    op[2 * lane]            = a0x * inv;
    op[2 * lane + 1]        = a0y * inv;
    op[2 * (lane + 32)]     = a1x * inv;
    op[2 * (lane + 32) + 1] = a1y * inv;
}

// ---------------- host orchestration ---------------------------------------
extern "C" void kernel_launch(void* const* d_in, const int* in_sizes, int n_in,
                              void* d_out, int out_size) {
    const float* query   = (const float*)d_in[0];
    const int*   ei      = (const int*)  d_in[1];
    const int*   mapping = (const int*)  d_in[2];
    const float* emb     = (const float*)d_in[3];
    const float* wn_w1 = (const float*)d_in[5];
    const float* wn_b1 = (const float*)d_in[6];
    const float* wn_w2 = (const float*)d_in[7];
    const float* wn_b2 = (const float*)d_in[8];
    const float* wp_w1 = (const float*)d_in[9];
    const float* wp_b1 = (const float*)d_in[10];
    const float* wp_w2 = (const float*)d_in[11];
    const float* wp_b2 = (const float*)d_in[12];
    const float* WQ    = (const float*)d_in[13];
    const float* WK    = (const float*)d_in[14];
    const float* WV    = (const float*)d_in[15];
    const float* WE    = (const float*)d_in[16];
    const float* bE    = (const float*)d_in[17];
    const float* Aw    = (const float*)d_in[18];
    float* out = (float*)d_out;

    float  *node_raw, *node_pos;
    __half *Xth, *Xh, *QKVh, *ehc, *e0c, *Ew1c, *e1c, *Ew2c;
    __half *Wpackth, *wn2th, *wp2th, *WEth;
    int *rowIdxQ, *rowIdx2, *nL2, *pm1, *pm0, *pc0, *pc2;
    cudaGetSymbolAddress((void**)&node_raw, g_node_raw);
    cudaGetSymbolAddress((void**)&node_pos, g_node_pos);
    cudaGetSymbolAddress((void**)&Xth,  g_Xth);
    cudaGetSymbolAddress((void**)&Xh,   g_Xh);
    cudaGetSymbolAddress((void**)&QKVh, g_QKVh);
    cudaGetSymbolAddress((void**)&ehc,  g_ehc);
    cudaGetSymbolAddress((void**)&e0c,  g_e0c);
    cudaGetSymbolAddress((void**)&Ew1c, g_Ew1c);
    cudaGetSymbolAddress((void**)&e1c,  g_e1c);
    cudaGetSymbolAddress((void**)&Ew2c, g_Ew2c);
    cudaGetSymbolAddress((void**)&Wpackth, g_Wpackth);
    cudaGetSymbolAddress((void**)&wn2th, g_wn2th);
    cudaGetSymbolAddress((void**)&wp2th, g_wp2th);
    cudaGetSymbolAddress((void**)&WEth,  g_WEth);
    cudaGetSymbolAddress((void**)&rowIdxQ, g_rowIdxQ);
    cudaGetSymbolAddress((void**)&rowIdx2, g_rowIdx2);
    cudaGetSymbolAddress((void**)&nL2, g_nL2);
    cudaGetSymbolAddress((void**)&pm1, g_m1);
    cudaGetSymbolAddress((void**)&pm0, g_m0);
    cudaGetSymbolAddress((void**)&pc0, g_c0);
    cudaGetSymbolAddress((void**)&pc2, g_c2);

    cudaFuncSetAttribute(gemm_h, cudaFuncAttributeMaxDynamicSharedMemorySize, GEMM_SMEM);
    cudaFuncSetAttribute(gemm_nodeg, cudaFuncAttributeMaxDynamicSharedMemorySize, GEMM_SMEM);
    cudaFuncSetAttribute(gemm_gather2, cudaFuncAttributeMaxDynamicSharedMemorySize, GEMM_SMEM);
    cudaFuncSetAttribute(k_l1combo, cudaFuncAttributeMaxDynamicSharedMemorySize, GEMM_SMEM);

    const int* srcp = ei;
    const int* dstp = ei + ET;
    const int T = 256;

    // ---- setup (reset + pack fused), frontier, CSR ----
    k_setup<<<(PACKTOT + T - 1) / T, T>>>(wn_w2, wp_w2, WE, WQ, WK, WV);
    k_flag1<<<1, BOUT>>>(mapping);
    k_build1<<<(ET + T - 1) / T, T>>>(srcp, dstp);
    k_fuse_et<<<(ET + T - 1) / T, T>>>(ei, emb);
    k_scan<<<1, 1024>>>();
    k_fill<<<(M0MAX + T - 1) / T, T>>>(dstp);
    k_sortbuild<<<(NN + T - 1) / T, T>>>();

    // ---- merged node + edge MLP hidden ----
    k_mlp_both<<<NBLK, T>>>(node_raw, wn_w1, wn_b1, emb, wp_w1, wp_b1);

    // ---- node path ----
    gemm_nodeg<<<dim3(DIM / 128, NN / 128), T, GEMM_SMEM>>>(Xth, wn2th, wn_b2,
                                                            node_pos, nL2, pc2);
    k_add_g<<<NBLK, T>>>(query, node_pos, Xh);

    // ---- compact edge feature chain ----
    gemm_h<<<dim3(DIM / 128, M0MAX / 128), T, GEMM_SMEM>>>(ehc, wp2th, wp_b2, e0c,
                                                           DIM, 1, pm0, 1);
    gemm_h<<<dim3((2 * DIM) / 128, M0MAX / 128), T, GEMM_SMEM>>>(e0c, WEth, bE, Ew1c,
                                                                 2 * DIM, 1, pm0, 1);

    // ======== layer 0 (merged Q + KV gathers) ========
    gemm_gather2<<<dim3(12, (4 * NN) / 128), T, GEMM_SMEM>>>(
        Xh, Wpackth, Wpackth + (size_t)512 * 512, QKVh, rowIdxQ, rowIdx2, pc0, pc2);
    k_edge0c<<<NBLK, T>>>(QKVh, srcp, dstp, Aw);
    k_msg0<<<NBLK, T>>>(QKVh, srcp, Xh);

    // ======== layer 1 (merged QKV gather + Ew2 GEMM) ========
    k_l1combo<<<dim3(20, C0GRID), T, GEMM_SMEM>>>(
        Xh, Wpackth + (size_t)1536 * 512, QKVh,
        e1c, WEth + 1024 * 512, bE + 2 * DIM, Ew2c, rowIdxQ, pc0, pm1);
    k_edge1c<<<NBLK, T>>>(QKVh, srcp, dstp, Aw + DIM);
    k_msg1<<<(BOUT * SQ * NH * 32) / T, T>>>(QKVh, srcp, mapping, out);
}